// round 9
// baseline (speedup 1.0000x reference)
#include <cuda_runtime.h>
#include <math.h>

// ---------------- problem capacities (fixed by the reference) ----------------
#define MAXN 100000
#define MAXE 1000000

// ---------------- device-global scratch (no runtime allocation) --------------
__device__ int   g_deg[MAXN];
__device__ int   g_off[MAXN];
__device__ int   g_cur[MAXN];
__device__ int   g_bsum[256];
__device__ int   g_csr[MAXE];
__device__ float g_y[MAXN * 64];
__device__ float g_z[MAXN * 64];
__device__ float g_h[MAXN * 64];

// ---------------- CSR build ----------------

__global__ void k_zero(int* __restrict__ deg, int n) {
    int i = blockIdx.x * blockDim.x + threadIdx.x;
    if (i < n) deg[i] = 0;
}

__global__ void k_hist(const int* __restrict__ ei, int E, int* __restrict__ deg) {
    int e = blockIdx.x * blockDim.x + threadIdx.x;
    if (e < E) atomicAdd(&deg[ei[E + e]], 1);
}

// Block-wise exclusive scan over 1024-wide chunks (Hillis–Steele inclusive, then -v)
__global__ void k_scan1(const int* __restrict__ deg, int* __restrict__ off,
                        int* __restrict__ bsum, int n) {
    __shared__ int s[1024];
    int t = threadIdx.x;
    int i = blockIdx.x * 1024 + t;
    int v = (i < n) ? deg[i] : 0;
    s[t] = v;
    __syncthreads();
    #pragma unroll
    for (int o = 1; o < 1024; o <<= 1) {
        int add = (t >= o) ? s[t - o] : 0;
        __syncthreads();
        s[t] += add;
        __syncthreads();
    }
    if (i < n) off[i] = s[t] - v;     // exclusive
    if (t == 1023) bsum[blockIdx.x] = s[1023];
}

__global__ void k_scan2(int* __restrict__ bsum, int nb) {
    if (threadIdx.x == 0 && blockIdx.x == 0) {
        int run = 0;
        for (int b = 0; b < nb; b++) { int v = bsum[b]; bsum[b] = run; run += v; }
    }
}

__global__ void k_scan3(int* __restrict__ off, int* __restrict__ cur,
                        const int* __restrict__ bsum, int n) {
    int i = blockIdx.x * blockDim.x + threadIdx.x;
    if (i < n) {
        int o = off[i] + bsum[i >> 10];
        off[i] = o;
        cur[i] = o;
    }
}

__global__ void k_scatter(const int* __restrict__ ei, int E,
                          int* __restrict__ cur, int* __restrict__ csr) {
    int e = blockIdx.x * blockDim.x + threadIdx.x;
    if (e < E) {
        int d   = ei[E + e];
        int pos = atomicAdd(&cur[d], 1);
        csr[pos] = ei[e];   // src
    }
}

// ---------------- fused dual GEMM: y = in @ Wl^T ; z = in @ Wr^T + b ----------
// 32 rows per block, 256 threads. Combined weight tile W[128][64] in shared
// (rows 0..63 = Wl, 64..127 = Wr), padded stride 68 floats so LDS.128 across
// lanes jc (rows jc + 32c) hits distinct banks: (jc*68+4k) % 32 = (4jc+4k) % 32.
__global__ __launch_bounds__(256) void k_gemm(
    const float* __restrict__ in,
    const float* __restrict__ wl, const float* __restrict__ wr,
    const float* __restrict__ bias,
    float* __restrict__ y, float* __restrict__ z, int n)
{
    __shared__ __align__(16) float sW[128][68];
    __shared__ __align__(16) float sX[32][64];

    int t    = threadIdx.x;
    int row0 = blockIdx.x * 32;

    // load combined weights (coalesced along k)
    for (int idx = t; idx < 128 * 64; idx += 256) {
        int j = idx >> 6, k = idx & 63;
        sW[j][k] = (j < 64) ? wl[idx] : wr[idx - 4096];
    }
    // load 32x64 input tile as float4
    for (int idx = t; idx < 32 * 16; idx += 256) {
        int r = idx >> 4, k4 = idx & 15;
        int row = row0 + r;
        float4 v = make_float4(0.f, 0.f, 0.f, 0.f);
        if (row < n) v = *(const float4*)&in[row * 64 + k4 * 4];
        *(float4*)&sX[r][k4 * 4] = v;
    }
    __syncthreads();

    int jc = t & 31;   // lane -> column within 32-wide group
    int rg = t >> 5;   // warp -> 4-row group (all lanes same rg -> sX broadcast)

    float acc[4][4];
    #pragma unroll
    for (int r = 0; r < 4; r++)
        #pragma unroll
        for (int c = 0; c < 4; c++) acc[r][c] = 0.f;

    #pragma unroll
    for (int k4 = 0; k4 < 16; k4++) {
        float4 xv[4], wv[4];
        #pragma unroll
        for (int r = 0; r < 4; r++) xv[r] = *(const float4*)&sX[rg * 4 + r][k4 * 4];
        #pragma unroll
        for (int c = 0; c < 4; c++) wv[c] = *(const float4*)&sW[jc + 32 * c][k4 * 4];
        #pragma unroll
        for (int r = 0; r < 4; r++)
            #pragma unroll
            for (int c = 0; c < 4; c++) {
                acc[r][c] += xv[r].x * wv[c].x;
                acc[r][c] += xv[r].y * wv[c].y;
                acc[r][c] += xv[r].z * wv[c].z;
                acc[r][c] += xv[r].w * wv[c].w;
            }
    }

    float b0 = __ldg(&bias[jc]);
    float b1 = __ldg(&bias[jc + 32]);
    #pragma unroll
    for (int r = 0; r < 4; r++) {
        int row = row0 + rg * 4 + r;
        if (row < n) {
            y[row * 64 + jc]      = acc[r][0];      // cols jc      of Wl
            y[row * 64 + jc + 32] = acc[r][1];      // cols jc+32   of Wl
            z[row * 64 + jc]      = acc[r][2] + b0; // cols jc      of Wr (+bias)
            z[row * 64 + jc + 32] = acc[r][3] + b1;
        }
    }
}

// ---------------- gather-mean aggregation: one warp per node ------------------
// h = relu( sum_{e in row} y[csr[e]] / max(deg,1) + z )
__global__ void k_agg(const float* __restrict__ y, const float* __restrict__ z,
                      const int* __restrict__ off, const int* __restrict__ deg,
                      const int* __restrict__ csr, float* __restrict__ h, int n)
{
    int gw = (blockIdx.x * blockDim.x + threadIdx.x) >> 5;
    if (gw >= n) return;
    int lane  = threadIdx.x & 31;
    int start = __ldg(&off[gw]);
    int d     = __ldg(&deg[gw]);

    float ax = 0.f, ay = 0.f;
    int e = 0;
    for (; e + 2 <= d; e += 2) {               // MLP=2 on the gather
        int s0 = __ldg(&csr[start + e]);
        int s1 = __ldg(&csr[start + e + 1]);
        float2 v0 = *(const float2*)&y[s0 * 64 + lane * 2];
        float2 v1 = *(const float2*)&y[s1 * 64 + lane * 2];
        ax += v0.x + v1.x;
        ay += v0.y + v1.y;
    }
    if (e < d) {
        int s0 = __ldg(&csr[start + e]);
        float2 v0 = *(const float2*)&y[s0 * 64 + lane * 2];
        ax += v0.x;
        ay += v0.y;
    }

    float inv = 1.f / fmaxf((float)d, 1.f);
    float2 zz = *(const float2*)&z[gw * 64 + lane * 2];
    float2 hv;
    hv.x = fmaxf(ax * inv + zz.x, 0.f);
    hv.y = fmaxf(ay * inv + zz.y, 0.f);
    *(float2*)&h[gw * 64 + lane * 2] = hv;
}

// ---------------- aggregation + output head fused -----------------------------
// g = relu(mean + z); out = sigmoid(dot(g, w_out) + b_out)
__global__ void k_agg_out(const float* __restrict__ y, const float* __restrict__ z,
                          const int* __restrict__ off, const int* __restrict__ deg,
                          const int* __restrict__ csr,
                          const float* __restrict__ wout, const float* __restrict__ bout,
                          float* __restrict__ out, int n)
{
    int gw = (blockIdx.x * blockDim.x + threadIdx.x) >> 5;
    if (gw >= n) return;
    int lane  = threadIdx.x & 31;
    int start = __ldg(&off[gw]);
    int d     = __ldg(&deg[gw]);

    float ax = 0.f, ay = 0.f;
    int e = 0;
    for (; e + 2 <= d; e += 2) {
        int s0 = __ldg(&csr[start + e]);
        int s1 = __ldg(&csr[start + e + 1]);
        float2 v0 = *(const float2*)&y[s0 * 64 + lane * 2];
        float2 v1 = *(const float2*)&y[s1 * 64 + lane * 2];
        ax += v0.x + v1.x;
        ay += v0.y + v1.y;
    }
    if (e < d) {
        int s0 = __ldg(&csr[start + e]);
        float2 v0 = *(const float2*)&y[s0 * 64 + lane * 2];
        ax += v0.x;
        ay += v0.y;
    }

    float inv = 1.f / fmaxf((float)d, 1.f);
    float2 zz = *(const float2*)&z[gw * 64 + lane * 2];
    float gx = fmaxf(ax * inv + zz.x, 0.f);
    float gy = fmaxf(ay * inv + zz.y, 0.f);

    float w0 = __ldg(&wout[lane * 2]);
    float w1 = __ldg(&wout[lane * 2 + 1]);
    float p  = gx * w0 + gy * w1;
    #pragma unroll
    for (int o = 16; o; o >>= 1) p += __shfl_xor_sync(0xffffffffu, p, o);
    if (lane == 0) {
        float t = p + __ldg(bout);
        out[gw] = 1.f / (1.f + expf(-t));
    }
}

// ---------------- launch ------------------------------------------------------
extern "C" void kernel_launch(void* const* d_in, const int* in_sizes, int n_in,
                              void* d_out, int out_size)
{
    const float* x    = (const float*)d_in[0];
    const int*   ei   = (const int*)  d_in[1];
    const float* w1l  = (const float*)d_in[2];
    const float* b1   = (const float*)d_in[3];
    const float* w1r  = (const float*)d_in[4];
    const float* w2l  = (const float*)d_in[5];
    const float* b2   = (const float*)d_in[6];
    const float* w2r  = (const float*)d_in[7];
    const float* wout = (const float*)d_in[8];
    const float* bout = (const float*)d_in[9];

    int n = in_sizes[0] / 64;
    int E = in_sizes[1] / 2;

    void *py, *pz, *ph, *pdeg, *poff, *pcur, *pbsum, *pcsr;
    cudaGetSymbolAddress(&py,   g_y);
    cudaGetSymbolAddress(&pz,   g_z);
    cudaGetSymbolAddress(&ph,   g_h);
    cudaGetSymbolAddress(&pdeg, g_deg);
    cudaGetSymbolAddress(&poff, g_off);
    cudaGetSymbolAddress(&pcur, g_cur);
    cudaGetSymbolAddress(&pbsum, g_bsum);
    cudaGetSymbolAddress(&pcsr, g_csr);

    int nb = (n + 1023) / 1024;

    // CSR build (reused by both convs)
    k_zero   <<<(n + 255) / 256, 256>>>((int*)pdeg, n);
    k_hist   <<<(E + 255) / 256, 256>>>(ei, E, (int*)pdeg);
    k_scan1  <<<nb, 1024>>>((const int*)pdeg, (int*)poff, (int*)pbsum, n);
    k_scan2  <<<1, 1>>>((int*)pbsum, nb);
    k_scan3  <<<(n + 255) / 256, 256>>>((int*)poff, (int*)pcur, (const int*)pbsum, n);
    k_scatter<<<(E + 255) / 256, 256>>>(ei, E, (int*)pcur, (int*)pcsr);

    // conv1: transform-then-aggregate
    k_gemm<<<(n + 31) / 32, 256>>>(x, w1l, w1r, b1, (float*)py, (float*)pz, n);
    k_agg <<<(n + 7) / 8, 256>>>((const float*)py, (const float*)pz,
                                 (const int*)poff, (const int*)pdeg, (const int*)pcsr,
                                 (float*)ph, n);

    // conv2 + output head
    k_gemm   <<<(n + 31) / 32, 256>>>((const float*)ph, w2l, w2r, b2,
                                      (float*)py, (float*)pz, n);
    k_agg_out<<<(n + 7) / 8, 256>>>((const float*)py, (const float*)pz,
                                    (const int*)poff, (const int*)pdeg, (const int*)pcsr,
                                    wout, bout, (float*)d_out, n);
}

// round 10
// speedup vs baseline: 1.0033x; 1.0033x over previous
#include <cuda_runtime.h>
#include <math.h>

// ---------------- problem capacities (fixed by the reference) ----------------
#define MAXN 100000
#define MAXE 1000000

// ---------------- device-global scratch (no runtime allocation) --------------
__device__ int   g_deg[MAXN];
__device__ int   g_off[MAXN];
__device__ int   g_cur[MAXN];
__device__ int   g_bsum[256];
__device__ int   g_csr[MAXE];
__device__ float g_y[MAXN * 64];
__device__ float g_z[MAXN * 64];
__device__ float g_h[MAXN * 64];

// ---------------- CSR build ----------------

__global__ void k_zero(int* __restrict__ deg, int n) {
    int i = blockIdx.x * blockDim.x + threadIdx.x;
    if (i < n) deg[i] = 0;
}

__global__ void k_hist(const int* __restrict__ ei, int E, int* __restrict__ deg) {
    int e = blockIdx.x * blockDim.x + threadIdx.x;
    if (e < E) atomicAdd(&deg[ei[E + e]], 1);
}

// Block-wise exclusive scan over 1024-wide chunks (Hillis–Steele inclusive, then -v)
__global__ void k_scan1(const int* __restrict__ deg, int* __restrict__ off,
                        int* __restrict__ bsum, int n) {
    __shared__ int s[1024];
    int t = threadIdx.x;
    int i = blockIdx.x * 1024 + t;
    int v = (i < n) ? deg[i] : 0;
    s[t] = v;
    __syncthreads();
    #pragma unroll
    for (int o = 1; o < 1024; o <<= 1) {
        int add = (t >= o) ? s[t - o] : 0;
        __syncthreads();
        s[t] += add;
        __syncthreads();
    }
    if (i < n) off[i] = s[t] - v;     // exclusive
    if (t == 1023) bsum[blockIdx.x] = s[1023];
}

__global__ void k_scan2(int* __restrict__ bsum, int nb) {
    if (threadIdx.x == 0 && blockIdx.x == 0) {
        int run = 0;
        for (int b = 0; b < nb; b++) { int v = bsum[b]; bsum[b] = run; run += v; }
    }
}

__global__ void k_scan3(int* __restrict__ off, int* __restrict__ cur,
                        const int* __restrict__ bsum, int n) {
    int i = blockIdx.x * blockDim.x + threadIdx.x;
    if (i < n) {
        int o = off[i] + bsum[i >> 10];
        off[i] = o;
        cur[i] = o;
    }
}

__global__ void k_scatter(const int* __restrict__ ei, int E,
                          int* __restrict__ cur, int* __restrict__ csr) {
    int e = blockIdx.x * blockDim.x + threadIdx.x;
    if (e < E) {
        int d   = ei[E + e];
        int pos = atomicAdd(&cur[d], 1);
        csr[pos] = ei[e];   // src
    }
}

// ---------------- fused dual GEMM: y = in @ Wl^T ; z = in @ Wr^T + b ----------
// 32 rows per block, 256 threads. Combined weight tile W[128][64] in shared
// (rows 0..63 = Wl, 64..127 = Wr), padded stride 68 floats so LDS.128 across
// lanes jc (rows jc + 32c) hits distinct banks: (jc*68+4k) % 32 = (4jc+4k) % 32.
__global__ __launch_bounds__(256) void k_gemm(
    const float* __restrict__ in,
    const float* __restrict__ wl, const float* __restrict__ wr,
    const float* __restrict__ bias,
    float* __restrict__ y, float* __restrict__ z, int n)
{
    __shared__ __align__(16) float sW[128][68];
    __shared__ __align__(16) float sX[32][64];

    int t    = threadIdx.x;
    int row0 = blockIdx.x * 32;

    // load combined weights (coalesced along k)
    for (int idx = t; idx < 128 * 64; idx += 256) {
        int j = idx >> 6, k = idx & 63;
        sW[j][k] = (j < 64) ? wl[idx] : wr[idx - 4096];
    }
    // load 32x64 input tile as float4
    for (int idx = t; idx < 32 * 16; idx += 256) {
        int r = idx >> 4, k4 = idx & 15;
        int row = row0 + r;
        float4 v = make_float4(0.f, 0.f, 0.f, 0.f);
        if (row < n) v = *(const float4*)&in[row * 64 + k4 * 4];
        *(float4*)&sX[r][k4 * 4] = v;
    }
    __syncthreads();

    int jc = t & 31;   // lane -> column within 32-wide group
    int rg = t >> 5;   // warp -> 4-row group (all lanes same rg -> sX broadcast)

    float acc[4][4];
    #pragma unroll
    for (int r = 0; r < 4; r++)
        #pragma unroll
        for (int c = 0; c < 4; c++) acc[r][c] = 0.f;

    #pragma unroll
    for (int k4 = 0; k4 < 16; k4++) {
        float4 xv[4], wv[4];
        #pragma unroll
        for (int r = 0; r < 4; r++) xv[r] = *(const float4*)&sX[rg * 4 + r][k4 * 4];
        #pragma unroll
        for (int c = 0; c < 4; c++) wv[c] = *(const float4*)&sW[jc + 32 * c][k4 * 4];
        #pragma unroll
        for (int r = 0; r < 4; r++)
            #pragma unroll
            for (int c = 0; c < 4; c++) {
                acc[r][c] += xv[r].x * wv[c].x;
                acc[r][c] += xv[r].y * wv[c].y;
                acc[r][c] += xv[r].z * wv[c].z;
                acc[r][c] += xv[r].w * wv[c].w;
            }
    }

    float b0 = __ldg(&bias[jc]);
    float b1 = __ldg(&bias[jc + 32]);
    #pragma unroll
    for (int r = 0; r < 4; r++) {
        int row = row0 + rg * 4 + r;
        if (row < n) {
            y[row * 64 + jc]      = acc[r][0];      // cols jc      of Wl
            y[row * 64 + jc + 32] = acc[r][1];      // cols jc+32   of Wl
            z[row * 64 + jc]      = acc[r][2] + b0; // cols jc      of Wr (+bias)
            z[row * 64 + jc + 32] = acc[r][3] + b1;
        }
    }
}

// ---------------- gather-mean aggregation: one warp per node ------------------
// h = relu( sum_{e in row} y[csr[e]] / max(deg,1) + z )
__global__ void k_agg(const float* __restrict__ y, const float* __restrict__ z,
                      const int* __restrict__ off, const int* __restrict__ deg,
                      const int* __restrict__ csr, float* __restrict__ h, int n)
{
    int gw = (blockIdx.x * blockDim.x + threadIdx.x) >> 5;
    if (gw >= n) return;
    int lane  = threadIdx.x & 31;
    int start = __ldg(&off[gw]);
    int d     = __ldg(&deg[gw]);

    float ax = 0.f, ay = 0.f;
    int e = 0;
    for (; e + 2 <= d; e += 2) {               // MLP=2 on the gather
        int s0 = __ldg(&csr[start + e]);
        int s1 = __ldg(&csr[start + e + 1]);
        float2 v0 = *(const float2*)&y[s0 * 64 + lane * 2];
        float2 v1 = *(const float2*)&y[s1 * 64 + lane * 2];
        ax += v0.x + v1.x;
        ay += v0.y + v1.y;
    }
    if (e < d) {
        int s0 = __ldg(&csr[start + e]);
        float2 v0 = *(const float2*)&y[s0 * 64 + lane * 2];
        ax += v0.x;
        ay += v0.y;
    }

    float inv = 1.f / fmaxf((float)d, 1.f);
    float2 zz = *(const float2*)&z[gw * 64 + lane * 2];
    float2 hv;
    hv.x = fmaxf(ax * inv + zz.x, 0.f);
    hv.y = fmaxf(ay * inv + zz.y, 0.f);
    *(float2*)&h[gw * 64 + lane * 2] = hv;
}

// ---------------- aggregation + output head fused -----------------------------
// g = relu(mean + z); out = sigmoid(dot(g, w_out) + b_out)
__global__ void k_agg_out(const float* __restrict__ y, const float* __restrict__ z,
                          const int* __restrict__ off, const int* __restrict__ deg,
                          const int* __restrict__ csr,
                          const float* __restrict__ wout, const float* __restrict__ bout,
                          float* __restrict__ out, int n)
{
    int gw = (blockIdx.x * blockDim.x + threadIdx.x) >> 5;
    if (gw >= n) return;
    int lane  = threadIdx.x & 31;
    int start = __ldg(&off[gw]);
    int d     = __ldg(&deg[gw]);

    float ax = 0.f, ay = 0.f;
    int e = 0;
    for (; e + 2 <= d; e += 2) {
        int s0 = __ldg(&csr[start + e]);
        int s1 = __ldg(&csr[start + e + 1]);
        float2 v0 = *(const float2*)&y[s0 * 64 + lane * 2];
        float2 v1 = *(const float2*)&y[s1 * 64 + lane * 2];
        ax += v0.x + v1.x;
        ay += v0.y + v1.y;
    }
    if (e < d) {
        int s0 = __ldg(&csr[start + e]);
        float2 v0 = *(const float2*)&y[s0 * 64 + lane * 2];
        ax += v0.x;
        ay += v0.y;
    }

    float inv = 1.f / fmaxf((float)d, 1.f);
    float2 zz = *(const float2*)&z[gw * 64 + lane * 2];
    float gx = fmaxf(ax * inv + zz.x, 0.f);
    float gy = fmaxf(ay * inv + zz.y, 0.f);

    float w0 = __ldg(&wout[lane * 2]);
    float w1 = __ldg(&wout[lane * 2 + 1]);
    float p  = gx * w0 + gy * w1;
    #pragma unroll
    for (int o = 16; o; o >>= 1) p += __shfl_xor_sync(0xffffffffu, p, o);
    if (lane == 0) {
        float t = p + __ldg(bout);
        out[gw] = 1.f / (1.f + expf(-t));
    }
}

// ---------------- launch ------------------------------------------------------
extern "C" void kernel_launch(void* const* d_in, const int* in_sizes, int n_in,
                              void* d_out, int out_size)
{
    const float* x    = (const float*)d_in[0];
    const int*   ei   = (const int*)  d_in[1];
    const float* w1l  = (const float*)d_in[2];
    const float* b1   = (const float*)d_in[3];
    const float* w1r  = (const float*)d_in[4];
    const float* w2l  = (const float*)d_in[5];
    const float* b2   = (const float*)d_in[6];
    const float* w2r  = (const float*)d_in[7];
    const float* wout = (const float*)d_in[8];
    const float* bout = (const float*)d_in[9];

    int n = in_sizes[0] / 64;
    int E = in_sizes[1] / 2;

    void *py, *pz, *ph, *pdeg, *poff, *pcur, *pbsum, *pcsr;
    cudaGetSymbolAddress(&py,   g_y);
    cudaGetSymbolAddress(&pz,   g_z);
    cudaGetSymbolAddress(&ph,   g_h);
    cudaGetSymbolAddress(&pdeg, g_deg);
    cudaGetSymbolAddress(&poff, g_off);
    cudaGetSymbolAddress(&pcur, g_cur);
    cudaGetSymbolAddress(&pbsum, g_bsum);
    cudaGetSymbolAddress(&pcsr, g_csr);

    int nb = (n + 1023) / 1024;

    // CSR build (reused by both convs)
    k_zero   <<<(n + 255) / 256, 256>>>((int*)pdeg, n);
    k_hist   <<<(E + 255) / 256, 256>>>(ei, E, (int*)pdeg);
    k_scan1  <<<nb, 1024>>>((const int*)pdeg, (int*)poff, (int*)pbsum, n);
    k_scan2  <<<1, 1>>>((int*)pbsum, nb);
    k_scan3  <<<(n + 255) / 256, 256>>>((int*)poff, (int*)pcur, (const int*)pbsum, n);
    k_scatter<<<(E + 255) / 256, 256>>>(ei, E, (int*)pcur, (int*)pcsr);

    // conv1: transform-then-aggregate
    k_gemm<<<(n + 31) / 32, 256>>>(x, w1l, w1r, b1, (float*)py, (float*)pz, n);
    k_agg <<<(n + 7) / 8, 256>>>((const float*)py, (const float*)pz,
                                 (const int*)poff, (const int*)pdeg, (const int*)pcsr,
                                 (float*)ph, n);

    // conv2 + output head
    k_gemm   <<<(n + 31) / 32, 256>>>((const float*)ph, w2l, w2r, b2,
                                      (float*)py, (float*)pz, n);
    k_agg_out<<<(n + 7) / 8, 256>>>((const float*)py, (const float*)pz,
                                    (const int*)poff, (const int*)pdeg, (const int*)pcsr,
                                    wout, bout, (float*)d_out, n);
}